// round 10
// baseline (speedup 1.0000x reference)
#include <cuda_runtime.h>

#define NHEADS 4
typedef unsigned long long u64;

// Scratch (allocation-free). Zero at module load; epilogue re-zeroes after
// reading so every graph replay observes zeros (deterministic).
__device__ float g_S[NHEADS][64];          // sum_n w[h,n] * u_n
__device__ float g_z[NHEADS];              // sum_n w[h,n]
__device__ unsigned int g_ctr;             // last-block-done counter

__device__ __forceinline__ float tanh_fast(float x) {
    float y; asm("tanh.approx.f32 %0, %1;" : "=f"(y) : "f"(x)); return y;
}
__device__ __forceinline__ float exp2_fast(float x) {
    float y; asm("ex2.approx.f32 %0, %1;" : "=f"(y) : "f"(x)); return y;
}
// ---- packed f32x2 helpers (ptxas never auto-fuses these from C++) ----
__device__ __forceinline__ u64 pack2(float lo, float hi) {
    u64 r; asm("mov.b64 %0, {%1, %2};" : "=l"(r) : "f"(lo), "f"(hi)); return r;
}
__device__ __forceinline__ void unpack2(u64 v, float& lo, float& hi) {
    asm("mov.b64 {%0, %1}, %2;" : "=f"(lo), "=f"(hi) : "l"(v));
}
__device__ __forceinline__ u64 fma2(u64 a, u64 b, u64 c) {
    u64 d; asm("fma.rn.f32x2 %0, %1, %2, %3;" : "=l"(d) : "l"(a), "l"(b), "l"(c)); return d;
}
__device__ __forceinline__ u64 mul2(u64 a, u64 b) {
    u64 d; asm("mul.rn.f32x2 %0, %1, %2;" : "=l"(d) : "l"(a), "l"(b)); return d;
}
__device__ __forceinline__ u64 add2(u64 a, u64 b) {
    u64 d; asm("add.rn.f32x2 %0, %1, %2;" : "=l"(d) : "l"(a), "l"(b)); return d;
}
__device__ __forceinline__ u64 shfl2_xor(u64 v, int m) {
    return __shfl_xor_sync(0xffffffffu, v, m);   // 2x SHFL.32
}

// ---------------------------------------------------------------------------
// Single fused kernel, 3 CTAs/SM, packed math.
// Prologue (per block): atil[h][j] = (scale*log2e) * (W2^T Wk_h^T q_h)[j].
// Main loop: warp cooperates; lane l owns hidden dims j0=l, j1=l+32.
//   8 points/round. Scores generated head-packed (f32x2 pairs (h0,h1),(h2,h3));
//   the m=16 butterfly stage is fused at generation using INPUT selection
//   (scores are linear in u, so selecting u inputs == selecting the score).
//   Stages 8/4/2 run packed (u64 shfl + add.f32x2); stage 1 scalar.
//   Lane l ends with score(pt=l>>2, h=l&3); one exp2; weights broadcast via
//   smem LDS.128; accumulation packed f32x2. Next group's inputs prefetched
//   before the butterfly so LDG latency overlaps the shfl chain.
// Epilogue: last finished block computes hbar/pooled/out, re-zeroes scratch.
//   (Race fix from R9 retained: all-thread fence + barrier BEFORE counting.)
// ---------------------------------------------------------------------------
__global__ void __launch_bounds__(256, 3)
main_kernel(const float* __restrict__ rr,
            const float* __restrict__ ri,
            const float* __restrict__ W1,
            const float* __restrict__ b1,
            const float* __restrict__ W2,
            const float* __restrict__ query,
            const float* __restrict__ ipw,
            const float* __restrict__ ipb,
            const float* __restrict__ b2,
            const float* __restrict__ opw,
            const float* __restrict__ opb,
            float* __restrict__ out,
            int N) {
    __shared__ float qsh[64];
    __shared__ float ash[NHEADS][64];     // reused as hbar in epilogue
    __shared__ float atil[NHEADS][64];
    __shared__ float wb[8][2][32];        // per-warp double-buffered weights
    __shared__ float invz[NHEADS];
    __shared__ bool  isLast;

    const int t    = threadIdx.x;
    const int lane = t & 31;
    const int wid  = t >> 5;

    // ---- prologue: q = query @ Wq^T + bq (4 threads per output) ----
    {
        int o = t >> 2, part = t & 3;
        float s = 0.f;
        const float* row = ipw + o * 64 + part * 16;
        const float* qp  = query + part * 16;
        #pragma unroll
        for (int i = 0; i < 16; ++i) s = fmaf(qp[i], row[i], s);
        s += __shfl_xor_sync(0xffffffffu, s, 1);
        s += __shfl_xor_sync(0xffffffffu, s, 2);
        if (part == 0) qsh[o] = s + ipb[o];
    }
    __syncthreads();
    // ---- a_h[c] = sum_d q[16h+d] * Wk[16h+d, c]  (Wk = ipw rows [64,128)) ----
    {
        int h = t >> 6, c = t & 63;
        float a = 0.f;
        #pragma unroll 4
        for (int d = 0; d < 16; ++d)
            a = fmaf(qsh[16 * h + d], ipw[(64 + 16 * h + d) * 64 + c], a);
        ash[h][c] = a;
    }
    __syncthreads();
    // ---- atil_h[c] = (0.25*log2e) * sum_m a_h[m] * W2[m,c] ----
    {
        const float SC = 0.25f * 1.4426950408889634f;  // scale * log2(e)
        int h = t >> 6, c = t & 63;
        float s = 0.f;
        #pragma unroll 8
        for (int m = 0; m < 64; ++m) s = fmaf(ash[h][m], W2[m * 64 + c], s);
        atil[h][c] = s * SC;
    }
    __syncthreads();

    // ---- per-lane constants (SiLU's 0.5 folded into W1/b1) ----
    const int j0 = lane, j1 = lane + 32;
    const float ka0 = 0.5f * W1[2 * j0], kb0 = 0.5f * W1[2 * j0 + 1], kc0 = 0.5f * b1[j0];
    const float ka1 = 0.5f * W1[2 * j1], kb1 = 0.5f * W1[2 * j1 + 1], kc1 = 0.5f * b1[j1];
    // Head-packed score vectors: (h0,h1) and (h2,h3) pairs for dims j0/j1.
    const u64 AH01_0 = pack2(atil[0][j0], atil[1][j0]);
    const u64 AH01_1 = pack2(atil[0][j1], atil[1][j1]);
    const u64 AH23_0 = pack2(atil[2][j0], atil[3][j0]);
    const u64 AH23_1 = pack2(atil[2][j1], atil[3][j1]);

    // Packed accumulators: (head pair) x (dim j0/j1)
    u64 acc0_01 = 0, acc0_23 = 0, acc1_01 = 0, acc1_23 = 0;
    float zloc = 0.f;   // lane-local sum of this lane's own em values

    const int gwarp  = (blockIdx.x * blockDim.x + t) >> 5;
    const int nwarps = (gridDim.x * blockDim.x) >> 5;
    const int G = N >> 3;
    const int chunk = (G + nwarps - 1) / nwarps;
    const int gs = gwarp * chunk;
    const int ge = min(G, gs + chunk);

    const float4* rr4 = (const float4*)rr;
    const float4* ri4 = (const float4*)ri;
    const bool hi16 = (lane & 16) != 0;
    const bool hi8  = (lane & 8) != 0;
    const bool hi4  = (lane & 4) != 0;
    const bool hi2  = (lane & 2) != 0;
    const bool hi1  = (lane & 1) != 0;

    float4 ra, rb, ia, ib;
    if (gs < ge) {
        ra = __ldg(rr4 + 2 * gs); rb = __ldg(rr4 + 2 * gs + 1);
        ia = __ldg(ri4 + 2 * gs); ib = __ldg(ri4 + 2 * gs + 1);
    }

    for (int g = gs; g < ge; ++g) {
        float re[8] = {ra.x, ra.y, ra.z, ra.w, rb.x, rb.y, rb.z, rb.w};
        float im[8] = {ia.x, ia.y, ia.z, ia.w, ib.x, ib.y, ib.z, ib.w};
        float u0[8], u1[8];
        #pragma unroll
        for (int pt = 0; pt < 8; ++pt) {
            float h0 = fmaf(ka0, re[pt], fmaf(kb0, im[pt], kc0));   // t/2
            float h1 = fmaf(ka1, re[pt], fmaf(kb1, im[pt], kc1));
            u0[pt] = fmaf(h0, tanh_fast(h0), h0);                   // silu
            u1[pt] = fmaf(h1, tanh_fast(h1), h1);
        }
        // Prefetch next group's inputs (re/im regs are dead now) so the LDG
        // latency overlaps the butterfly's shfl chain.
        {
            int gn = (g + 1 < ge) ? (g + 1) : g;
            ra = __ldg(rr4 + 2 * gn); rb = __ldg(rr4 + 2 * gn + 1);
            ia = __ldg(ri4 + 2 * gn); ib = __ldg(ri4 + 2 * gn + 1);
        }
        // Head-packed score generation with fused m=16 stage.
        // Value index v = pt*4+h. Pair (v, v+16) = (pt, pt+4). Scores are
        // linear in (u0,u1), so select the u INPUTS (4 scalar SELs) instead
        // of the packed outputs, then compute keep/send scores directly.
        u64 Q[8];   // Q[k] holds packed values (2k, 2k+1)
        #pragma unroll
        for (int pp = 0; pp < 4; ++pp) {
            float a0 = hi16 ? u0[pp + 4] : u0[pp];
            float a1 = hi16 ? u1[pp + 4] : u1[pp];
            float b0 = hi16 ? u0[pp]     : u0[pp + 4];
            float b1v = hi16 ? u1[pp]    : u1[pp + 4];
            u64 KD0 = pack2(a0, a0), KD1 = pack2(a1, a1);
            u64 SD0 = pack2(b0, b0), SD1 = pack2(b1v, b1v);
            u64 k01 = fma2(AH01_0, KD0, mul2(AH01_1, KD1));
            u64 k23 = fma2(AH23_0, KD0, mul2(AH23_1, KD1));
            u64 s01 = fma2(AH01_0, SD0, mul2(AH01_1, SD1));
            u64 s23 = fma2(AH23_0, SD0, mul2(AH23_1, SD1));
            Q[2 * pp]     = add2(k01, shfl2_xor(s01, 16));
            Q[2 * pp + 1] = add2(k23, shfl2_xor(s23, 16));
        }
        // Stage m=8: value v pairs v+8 -> Q[k] with Q[k+4], k<4.
        #pragma unroll
        for (int k = 0; k < 4; ++k) {
            u64 kk = hi8 ? Q[k + 4] : Q[k];
            u64 ss = hi8 ? Q[k] : Q[k + 4];
            Q[k] = add2(kk, shfl2_xor(ss, 8));
        }
        // Stage m=4: Q[k] with Q[k+2], k<2.
        #pragma unroll
        for (int k = 0; k < 2; ++k) {
            u64 kk = hi4 ? Q[k + 2] : Q[k];
            u64 ss = hi4 ? Q[k] : Q[k + 2];
            Q[k] = add2(kk, shfl2_xor(ss, 4));
        }
        // Stage m=2: Q[0] with Q[1].
        {
            u64 kk = hi2 ? Q[1] : Q[0];
            u64 ss = hi2 ? Q[0] : Q[1];
            Q[0] = add2(kk, shfl2_xor(ss, 2));
        }
        // Stage m=1: values 0,1 are lo/hi of Q[0] -> scalar finish.
        float e0, e1; unpack2(Q[0], e0, e1);
        float keep = hi1 ? e1 : e0, send = hi1 ? e0 : e1;
        float sfin = keep + __shfl_xor_sync(0xffffffffu, send, 1);
        float em = exp2_fast(sfin);   // exp(score(pt=lane>>2, h=lane&3))
        zloc += em;
        // Broadcast the 32 weights through smem (double-buffered per warp).
        wb[wid][g & 1][lane] = em;
        __syncwarp();
        const float4* wp = (const float4*)&wb[wid][g & 1][0];
        #pragma unroll
        for (int pt = 0; pt < 8; ++pt) {
            float4 w4 = wp[pt];                      // weights h=0..3 for pt
            u64 W01 = pack2(w4.x, w4.y), W23 = pack2(w4.z, w4.w);
            u64 D0 = pack2(u0[pt], u0[pt]), D1 = pack2(u1[pt], u1[pt]);
            acc0_01 = fma2(W01, D0, acc0_01);
            acc0_23 = fma2(W23, D0, acc0_23);
            acc1_01 = fma2(W01, D1, acc1_01);
            acc1_23 = fma2(W23, D1, acc1_23);
        }
    }

    float acc0[NHEADS], acc1[NHEADS];
    unpack2(acc0_01, acc0[0], acc0[1]); unpack2(acc0_23, acc0[2], acc0[3]);
    unpack2(acc1_01, acc1[0], acc1[1]); unpack2(acc1_23, acc1[2], acc1[3]);

    // Tail points (N % 8): warp 0 only, scalar path (atil read from smem).
    float ztl[NHEADS] = {0.f, 0.f, 0.f, 0.f};
    if (gwarp == 0) {
        for (int n = (G << 3); n < N; ++n) {
            float re = rr[n], im = ri[n];
            float h0 = fmaf(ka0, re, fmaf(kb0, im, kc0));
            float h1 = fmaf(ka1, re, fmaf(kb1, im, kc1));
            float v0 = fmaf(h0, tanh_fast(h0), h0);
            float v1 = fmaf(h1, tanh_fast(h1), h1);
            #pragma unroll
            for (int h = 0; h < NHEADS; ++h) {
                float s = fmaf(atil[h][j0], v0, atil[h][j1] * v1);
                #pragma unroll
                for (int m = 16; m >= 1; m >>= 1)
                    s += __shfl_xor_sync(0xffffffffu, s, m);
                float w = exp2_fast(s);
                ztl[h] += w;
                acc0[h] = fmaf(w, v0, acc0[h]);
                acc1[h] = fmaf(w, v1, acc1[h]);
            }
        }
    }

    // Commit warp partials (lane-distinct addresses; no intra-warp contention)
    #pragma unroll
    for (int h = 0; h < NHEADS; ++h) {
        atomicAdd(&g_S[h][j0], acc0[h]);
        atomicAdd(&g_S[h][j1], acc1[h]);
    }
    // zloc at lane l belongs to head h=l&3; same-h lanes differ in bits {2,3,4}
    float zs = zloc + __shfl_xor_sync(0xffffffffu, zloc, 16);
    zs += __shfl_xor_sync(0xffffffffu, zs, 8);
    zs += __shfl_xor_sync(0xffffffffu, zs, 4);
    if (lane < NHEADS) atomicAdd(&g_z[lane], zs);
    if (gwarp == 0 && lane == 0) {
        #pragma unroll
        for (int h = 0; h < NHEADS; ++h) atomicAdd(&g_z[h], ztl[h]);
    }

    // ---- epilogue: last block computes the output -------------------------
    // RACE FIX: every thread fences its own atomics, then the block barrier
    // guarantees ALL warps of this block have fenced before thread 0 counts
    // the block as done.
    __threadfence();
    __syncthreads();
    if (t == 0) {
        unsigned v = atomicAdd(&g_ctr, 1u);
        isLast = (v == gridDim.x - 1);
        if (isLast) g_ctr = 0;           // all blocks incremented; safe reset
    }
    __syncthreads();
    if (!isLast) return;

    float* hbar = &ash[0][0];            // reuse [4][64]
    float* pooled = qsh;                 // reuse [64]
    if (t < NHEADS) invz[t] = __frcp_rn(__ldcg(&g_z[t]));
    __syncthreads();
    {
        int h = t >> 6, j = t & 63;
        float s = 0.f;
        #pragma unroll 8
        for (int m = 0; m < 64; ++m)
            s = fmaf(W2[j * 64 + m], __ldcg(&g_S[h][m]), s);
        hbar[h * 64 + j] = fmaf(s, invz[h], b2[j]);
    }
    __syncthreads();
    // scratch reset for next graph replay (all reads of g_S/g_z done)
    ((float*)g_S)[t] = 0.f;
    if (t < NHEADS) g_z[t] = 0.f;
    if (t < 64) {
        int h = t >> 4;
        float s = ipb[128 + t];          // Wv row (128+t) dot hbar_h + bv
        #pragma unroll 8
        for (int m = 0; m < 64; ++m)
            s = fmaf(ipw[(128 + t) * 64 + m], hbar[h * 64 + m], s);
        pooled[t] = s;
    }
    __syncthreads();
    if (t < 64) {
        float s = opb[t];
        #pragma unroll 8
        for (int k = 0; k < 64; ++k) s = fmaf(opw[t * 64 + k], pooled[k], s);
        out[t] = s;
    }
}

// ---------------------------------------------------------------------------
extern "C" void kernel_launch(void* const* d_in, const int* in_sizes, int n_in,
                              void* d_out, int out_size) {
    // Inputs (metadata order): rho_real, rho_imag, l_A, l_B, [Z_A, Z_B,]
    // W1, b1, W2, b2, query, in_proj_w, in_proj_b, out_proj_w, out_proj_b.
    const float* rr    = (const float*)d_in[0];
    const float* ri    = (const float*)d_in[1];
    const float* W1    = (const float*)d_in[n_in - 9];
    const float* b1    = (const float*)d_in[n_in - 8];
    const float* W2    = (const float*)d_in[n_in - 7];
    const float* b2    = (const float*)d_in[n_in - 6];
    const float* query = (const float*)d_in[n_in - 5];
    const float* ipw   = (const float*)d_in[n_in - 4];
    const float* ipb   = (const float*)d_in[n_in - 3];
    const float* opw   = (const float*)d_in[n_in - 2];
    const float* opb   = (const float*)d_in[n_in - 1];
    int N = in_sizes[0];

    main_kernel<<<444, 256>>>(rr, ri, W1, b1, W2, query, ipw, ipb,
                              b2, opw, opb, (float*)d_out, N);
}

// round 11
// speedup vs baseline: 1.0893x; 1.0893x over previous
#include <cuda_runtime.h>

#define NHEADS 4
#define PITCH 68   // floats per padded row (272B): 4-bank rotation per row
typedef unsigned long long u64;

// Scratch (allocation-free). Zero at module load; epilogue re-zeroes after
// reading so every graph replay observes zeros (deterministic).
__device__ float g_S[NHEADS][64];          // sum_n w[h,n] * u_n
__device__ float g_z[NHEADS];              // sum_n w[h,n]
__device__ unsigned int g_ctr;             // last-block-done counter

__device__ __forceinline__ float tanh_fast(float x) {
    float y; asm("tanh.approx.f32 %0, %1;" : "=f"(y) : "f"(x)); return y;
}
__device__ __forceinline__ float exp2_fast(float x) {
    float y; asm("ex2.approx.f32 %0, %1;" : "=f"(y) : "f"(x)); return y;
}
// ---- packed f32x2 helpers ----
__device__ __forceinline__ u64 pack2(float lo, float hi) {
    u64 r; asm("mov.b64 %0, {%1, %2};" : "=l"(r) : "f"(lo), "f"(hi)); return r;
}
__device__ __forceinline__ void unpack2(u64 v, float& lo, float& hi) {
    asm("mov.b64 {%0, %1}, %2;" : "=f"(lo), "=f"(hi) : "l"(v));
}
__device__ __forceinline__ u64 fma2(u64 a, u64 b, u64 c) {
    u64 d; asm("fma.rn.f32x2 %0, %1, %2, %3;" : "=l"(d) : "l"(a), "l"(b), "l"(c)); return d;
}

// ---------------------------------------------------------------------------
// Single fused kernel, 2 CTAs/SM (no reg cap -> no spills), grid 296.
// Prologue (per block): atil[h][j] = (scale*log2e)*(W2^T Wk_h^T q_h)[j], padded.
// Main loop: warp cooperates; lane l owns hidden dims j0=l, j1=l+32.
//   16 points/round. Lanes store their u values into a padded smem tile
//   (transpose), then each lane computes TWO scores directly:
//     (pt = l>>2, h = l&3) and (pt+8, same h)
//   as 64-long dots using LDS.128 -> f32x2 FMA (no butterfly, no SHFL chain,
//   no pack-MOV churn). exp2 per score; 64 weights broadcast via smem
//   LDS.128 (uniform address); accumulation packed f32x2.
// Epilogue: last finished block computes hbar/pooled/out, re-zeroes scratch.
//   (Race fix: all-thread fence + __syncthreads BEFORE counting the block.)
// ---------------------------------------------------------------------------
__global__ void __launch_bounds__(256, 2)
main_kernel(const float* __restrict__ rr,
            const float* __restrict__ ri,
            const float* __restrict__ W1,
            const float* __restrict__ b1,
            const float* __restrict__ W2,
            const float* __restrict__ query,
            const float* __restrict__ ipw,
            const float* __restrict__ ipb,
            const float* __restrict__ b2,
            const float* __restrict__ opw,
            const float* __restrict__ opb,
            float* __restrict__ out,
            int N) {
    __shared__ float qsh[64];
    __shared__ float ash[NHEADS][64];        // reused as hbar in epilogue
    __shared__ float atil_p[NHEADS * PITCH]; // padded score vectors
    __shared__ float u_sm[8][16 * PITCH];    // per-warp u tile [pt][dim]
    __shared__ float wb[8][64];              // per-warp weights
    __shared__ float invz[NHEADS];
    __shared__ bool  isLast;

    const int t    = threadIdx.x;
    const int lane = t & 31;
    const int wid  = t >> 5;

    // ---- prologue: q = query @ Wq^T + bq (4 threads per output) ----
    {
        int o = t >> 2, part = t & 3;
        float s = 0.f;
        const float* row = ipw + o * 64 + part * 16;
        const float* qp  = query + part * 16;
        #pragma unroll
        for (int i = 0; i < 16; ++i) s = fmaf(qp[i], row[i], s);
        s += __shfl_xor_sync(0xffffffffu, s, 1);
        s += __shfl_xor_sync(0xffffffffu, s, 2);
        if (part == 0) qsh[o] = s + ipb[o];
    }
    __syncthreads();
    // ---- a_h[c] = sum_d q[16h+d] * Wk[16h+d, c]  (Wk = ipw rows [64,128)) ----
    {
        int h = t >> 6, c = t & 63;
        float a = 0.f;
        #pragma unroll 4
        for (int d = 0; d < 16; ++d)
            a = fmaf(qsh[16 * h + d], ipw[(64 + 16 * h + d) * 64 + c], a);
        ash[h][c] = a;
    }
    __syncthreads();
    // ---- atil_p[h][c] = (0.25*log2e) * sum_m a_h[m] * W2[m,c] ----
    {
        const float SC = 0.25f * 1.4426950408889634f;  // scale * log2(e)
        int h = t >> 6, c = t & 63;
        float s = 0.f;
        #pragma unroll 8
        for (int m = 0; m < 64; ++m) s = fmaf(ash[h][m], W2[m * 64 + c], s);
        atil_p[h * PITCH + c] = s * SC;
    }
    __syncthreads();

    // ---- per-lane constants (SiLU's 0.5 folded into W1/b1) ----
    const int j0 = lane, j1 = lane + 32;
    const float ka0 = 0.5f * W1[2 * j0], kb0 = 0.5f * W1[2 * j0 + 1], kc0 = 0.5f * b1[j0];
    const float ka1 = 0.5f * W1[2 * j1], kb1 = 0.5f * W1[2 * j1 + 1], kc1 = 0.5f * b1[j1];

    // Packed accumulators: (head pair) x (dim j0/j1)
    u64 acc0_01 = 0, acc0_23 = 0, acc1_01 = 0, acc1_23 = 0;
    float zloc = 0.f;   // lane-local sum of this lane's own em values

    const int gwarp  = (blockIdx.x * blockDim.x + t) >> 5;
    const int nwarps = (gridDim.x * blockDim.x) >> 5;
    const int G = N >> 4;                       // groups of 16 points
    const int chunk = (G + nwarps - 1) / nwarps;
    const int gs = gwarp * chunk;
    const int ge = min(G, gs + chunk);

    const float4* rr4 = (const float4*)rr;
    const float4* ri4 = (const float4*)ri;
    float* usm = &u_sm[wid][0];
    float* wbp = &wb[wid][0];
    const float* arow = atil_p + (lane & 3) * PITCH;
    const float* ur0  = usm + (lane >> 2) * PITCH;
    const float* ur1  = ur0 + 8 * PITCH;

    for (int g = gs; g < ge; ++g) {
        // ---- load 16 points (8x LDG.128, warp-uniform addresses) ----
        float4 r0 = __ldg(rr4 + 4 * g),     r1 = __ldg(rr4 + 4 * g + 1);
        float4 r2 = __ldg(rr4 + 4 * g + 2), r3 = __ldg(rr4 + 4 * g + 3);
        float4 i0 = __ldg(ri4 + 4 * g),     i1 = __ldg(ri4 + 4 * g + 1);
        float4 i2 = __ldg(ri4 + 4 * g + 2), i3 = __ldg(ri4 + 4 * g + 3);
        float re[16] = {r0.x, r0.y, r0.z, r0.w, r1.x, r1.y, r1.z, r1.w,
                        r2.x, r2.y, r2.z, r2.w, r3.x, r3.y, r3.z, r3.w};
        float im[16] = {i0.x, i0.y, i0.z, i0.w, i1.x, i1.y, i1.z, i1.w,
                        i2.x, i2.y, i2.z, i2.w, i3.x, i3.y, i3.z, i3.w};
        // ---- MLP + SiLU, and store u into the smem tile ----
        float u0s[16], u1s[16];
        #pragma unroll
        for (int pt = 0; pt < 16; ++pt) {
            float h0 = fmaf(ka0, re[pt], fmaf(kb0, im[pt], kc0));   // t/2
            float h1 = fmaf(ka1, re[pt], fmaf(kb1, im[pt], kc1));
            float v0 = fmaf(h0, tanh_fast(h0), h0);                 // silu
            float v1 = fmaf(h1, tanh_fast(h1), h1);
            u0s[pt] = v0; u1s[pt] = v1;
            usm[pt * PITCH + j0] = v0;
            usm[pt * PITCH + j1] = v1;
        }
        __syncwarp();
        // ---- two direct 64-long dots per lane (this lane's own scores) ----
        u64 dA0 = 0, dA1 = 0, dB0 = 0, dB1 = 0;
        #pragma unroll
        for (int i = 0; i < 64; i += 4) {
            ulonglong2 aa = *(const ulonglong2*)(arow + i);   // atil[h][i..i+3]
            ulonglong2 ua = *(const ulonglong2*)(ur0 + i);    // u[pt][i..i+3]
            ulonglong2 ub = *(const ulonglong2*)(ur1 + i);    // u[pt+8][..]
            dA0 = fma2(aa.x, ua.x, dA0); dA1 = fma2(aa.y, ua.y, dA1);
            dB0 = fma2(aa.x, ub.x, dB0); dB1 = fma2(aa.y, ub.y, dB1);
        }
        float xa, xb, xc, xd;
        unpack2(dA0, xa, xb); unpack2(dA1, xc, xd);
        float sA = (xa + xb) + (xc + xd);
        unpack2(dB0, xa, xb); unpack2(dB1, xc, xd);
        float sB = (xa + xb) + (xc + xd);
        float emA = exp2_fast(sA);       // exp(score(pt=lane>>2,   h=lane&3))
        float emB = exp2_fast(sB);       // exp(score(pt=8+lane>>2, h=lane&3))
        zloc += emA + emB;
        wbp[lane] = emA; wbp[lane + 32] = emB;
        __syncwarp();
        // ---- accumulate: weights broadcast via uniform-address LDS.128 ----
        const float4* wp = (const float4*)wbp;
        #pragma unroll
        for (int pt = 0; pt < 16; ++pt) {
            float4 w4 = wp[pt];                      // weights h=0..3 for pt
            u64 W01 = pack2(w4.x, w4.y), W23 = pack2(w4.z, w4.w);
            u64 D0 = pack2(u0s[pt], u0s[pt]), D1 = pack2(u1s[pt], u1s[pt]);
            acc0_01 = fma2(W01, D0, acc0_01);
            acc0_23 = fma2(W23, D0, acc0_23);
            acc1_01 = fma2(W01, D1, acc1_01);
            acc1_23 = fma2(W23, D1, acc1_23);
        }
    }

    float acc0[NHEADS], acc1[NHEADS];
    unpack2(acc0_01, acc0[0], acc0[1]); unpack2(acc0_23, acc0[2], acc0[3]);
    unpack2(acc1_01, acc1[0], acc1[1]); unpack2(acc1_23, acc1[2], acc1[3]);

    // Tail points (N % 16): warp 0 only, scalar butterfly path.
    float ztl[NHEADS] = {0.f, 0.f, 0.f, 0.f};
    if (gwarp == 0) {
        for (int n = (G << 4); n < N; ++n) {
            float re = rr[n], im = ri[n];
            float h0 = fmaf(ka0, re, fmaf(kb0, im, kc0));
            float h1 = fmaf(ka1, re, fmaf(kb1, im, kc1));
            float v0 = fmaf(h0, tanh_fast(h0), h0);
            float v1 = fmaf(h1, tanh_fast(h1), h1);
            #pragma unroll
            for (int h = 0; h < NHEADS; ++h) {
                float s = fmaf(atil_p[h * PITCH + j0], v0,
                               atil_p[h * PITCH + j1] * v1);
                #pragma unroll
                for (int m = 16; m >= 1; m >>= 1)
                    s += __shfl_xor_sync(0xffffffffu, s, m);
                float w = exp2_fast(s);
                ztl[h] += w;
                acc0[h] = fmaf(w, v0, acc0[h]);
                acc1[h] = fmaf(w, v1, acc1[h]);
            }
        }
    }

    // Commit warp partials (lane-distinct addresses; no intra-warp contention)
    #pragma unroll
    for (int h = 0; h < NHEADS; ++h) {
        atomicAdd(&g_S[h][j0], acc0[h]);
        atomicAdd(&g_S[h][j1], acc1[h]);
    }
    // zloc at lane l belongs to head h=l&3; same-h lanes differ in bits {2,3,4}
    float zs = zloc + __shfl_xor_sync(0xffffffffu, zloc, 16);
    zs += __shfl_xor_sync(0xffffffffu, zs, 8);
    zs += __shfl_xor_sync(0xffffffffu, zs, 4);
    if (lane < NHEADS) atomicAdd(&g_z[lane], zs);
    if (gwarp == 0 && lane == 0) {
        #pragma unroll
        for (int h = 0; h < NHEADS; ++h) atomicAdd(&g_z[h], ztl[h]);
    }

    // ---- epilogue: last block computes the output -------------------------
    // RACE FIX: every thread fences its own atomics; the block barrier then
    // guarantees ALL warps of this block have fenced before thread 0 counts
    // the block as done.
    __threadfence();
    __syncthreads();
    if (t == 0) {
        unsigned v = atomicAdd(&g_ctr, 1u);
        isLast = (v == gridDim.x - 1);
        if (isLast) g_ctr = 0;           // all blocks incremented; safe reset
    }
    __syncthreads();
    if (!isLast) return;

    float* hbar = &ash[0][0];            // reuse [4][64]
    float* pooled = qsh;                 // reuse [64]
    if (t < NHEADS) invz[t] = __frcp_rn(__ldcg(&g_z[t]));
    __syncthreads();
    {
        int h = t >> 6, j = t & 63;
        float s = 0.f;
        #pragma unroll 8
        for (int m = 0; m < 64; ++m)
            s = fmaf(W2[j * 64 + m], __ldcg(&g_S[h][m]), s);
        hbar[h * 64 + j] = fmaf(s, invz[h], b2[j]);
    }
    __syncthreads();
    // scratch reset for next graph replay (all reads of g_S/g_z done)
    ((float*)g_S)[t] = 0.f;
    if (t < NHEADS) g_z[t] = 0.f;
    if (t < 64) {
        int h = t >> 4;
        float s = ipb[128 + t];          // Wv row (128+t) dot hbar_h + bv
        #pragma unroll 8
        for (int m = 0; m < 64; ++m)
            s = fmaf(ipw[(128 + t) * 64 + m], hbar[h * 64 + m], s);
        pooled[t] = s;
    }
    __syncthreads();
    if (t < 64) {
        float s = opb[t];
        #pragma unroll 8
        for (int k = 0; k < 64; ++k) s = fmaf(opw[t * 64 + k], pooled[k], s);
        out[t] = s;
    }
}

// ---------------------------------------------------------------------------
extern "C" void kernel_launch(void* const* d_in, const int* in_sizes, int n_in,
                              void* d_out, int out_size) {
    // Inputs (metadata order): rho_real, rho_imag, l_A, l_B, [Z_A, Z_B,]
    // W1, b1, W2, b2, query, in_proj_w, in_proj_b, out_proj_w, out_proj_b.
    const float* rr    = (const float*)d_in[0];
    const float* ri    = (const float*)d_in[1];
    const float* W1    = (const float*)d_in[n_in - 9];
    const float* b1    = (const float*)d_in[n_in - 8];
    const float* W2    = (const float*)d_in[n_in - 7];
    const float* b2    = (const float*)d_in[n_in - 6];
    const float* query = (const float*)d_in[n_in - 5];
    const float* ipw   = (const float*)d_in[n_in - 4];
    const float* ipb   = (const float*)d_in[n_in - 3];
    const float* opw   = (const float*)d_in[n_in - 2];
    const float* opb   = (const float*)d_in[n_in - 1];
    int N = in_sizes[0];

    main_kernel<<<296, 256>>>(rr, ri, W1, b1, W2, query, ipw, ipb,
                              b2, opw, opb, (float*)d_out, N);
}

// round 12
// speedup vs baseline: 1.1604x; 1.0652x over previous
#include <cuda_runtime.h>

#define NHEADS 4
typedef unsigned long long u64;

// Scratch (allocation-free). Zero at module load; epilogue re-zeroes after
// reading so every graph replay observes zeros (deterministic).
__device__ float g_S[NHEADS][64];          // sum_n w[h,n] * u_n
__device__ float g_z[NHEADS];              // sum_n w[h,n]
__device__ unsigned int g_ctr;             // last-block-done counter

__device__ __forceinline__ float tanh_fast(float x) {
    float y; asm("tanh.approx.f32 %0, %1;" : "=f"(y) : "f"(x)); return y;
}
__device__ __forceinline__ float exp2_fast(float x) {
    float y; asm("ex2.approx.f32 %0, %1;" : "=f"(y) : "f"(x)); return y;
}
// ---- packed f32x2 helpers (accumulation only) ----
__device__ __forceinline__ u64 pack2(float lo, float hi) {
    u64 r; asm("mov.b64 %0, {%1, %2};" : "=l"(r) : "f"(lo), "f"(hi)); return r;
}
__device__ __forceinline__ void unpack2(u64 v, float& lo, float& hi) {
    asm("mov.b64 {%0, %1}, %2;" : "=f"(lo), "=f"(hi) : "l"(v));
}
__device__ __forceinline__ u64 fma2(u64 a, u64 b, u64 c) {
    u64 d; asm("fma.rn.f32x2 %0, %1, %2, %3;" : "=l"(d) : "l"(a), "l"(b), "l"(c)); return d;
}

// ---------------------------------------------------------------------------
// Single fused kernel (R7 structure + dual-chain ILP).
// Prologue (per block): atil[h][j] = (scale*log2e)*(W2^T Wk_h^T q_h)[j].
// Main loop: warp cooperates; lane l owns hidden dims j0=l, j1=l+32.
//   16 points/iteration as TWO independent 8-pt halves (A and B). Their
//   MLPs, fused-m16 score stages and butterflies share no registers, so the
//   scheduler interleaves the two shfl chains (latency hiding). All 8
//   LDG.128 issue at the top so one memory wait serves 16 points.
//   Lane l ends with score(pt=l>>2, h=l&3) per half; one exp2 per half;
//   weights broadcast via smem LDS.128 (parity double-buffered, single
//   __syncwarp per 16 points); accumulation packed f32x2.
// Epilogue: last finished block computes hbar/pooled/out, re-zeroes scratch.
//   (Race fix retained: all-thread fence + __syncthreads BEFORE counting.)
// ---------------------------------------------------------------------------
__global__ void __launch_bounds__(256, 2)
main_kernel(const float* __restrict__ rr,
            const float* __restrict__ ri,
            const float* __restrict__ W1,
            const float* __restrict__ b1,
            const float* __restrict__ W2,
            const float* __restrict__ query,
            const float* __restrict__ ipw,
            const float* __restrict__ ipb,
            const float* __restrict__ b2,
            const float* __restrict__ opw,
            const float* __restrict__ opb,
            float* __restrict__ out,
            int N) {
    __shared__ float qsh[64];
    __shared__ float ash[NHEADS][64];     // reused as hbar in epilogue
    __shared__ float atil[NHEADS][64];
    __shared__ float wb[8][2][64];        // per-warp parity-buffered weights
    __shared__ float invz[NHEADS];
    __shared__ bool  isLast;

    const int t    = threadIdx.x;
    const int lane = t & 31;
    const int wid  = t >> 5;

    // ---- prologue: q = query @ Wq^T + bq (4 threads per output) ----
    {
        int o = t >> 2, part = t & 3;
        float s = 0.f;
        const float* row = ipw + o * 64 + part * 16;
        const float* qp  = query + part * 16;
        #pragma unroll
        for (int i = 0; i < 16; ++i) s = fmaf(qp[i], row[i], s);
        s += __shfl_xor_sync(0xffffffffu, s, 1);
        s += __shfl_xor_sync(0xffffffffu, s, 2);
        if (part == 0) qsh[o] = s + ipb[o];
    }
    __syncthreads();
    // ---- a_h[c] = sum_d q[16h+d] * Wk[16h+d, c]  (Wk = ipw rows [64,128)) ----
    {
        int h = t >> 6, c = t & 63;
        float a = 0.f;
        #pragma unroll 4
        for (int d = 0; d < 16; ++d)
            a = fmaf(qsh[16 * h + d], ipw[(64 + 16 * h + d) * 64 + c], a);
        ash[h][c] = a;
    }
    __syncthreads();
    // ---- atil_h[c] = (0.25*log2e) * sum_m a_h[m] * W2[m,c] ----
    {
        const float SC = 0.25f * 1.4426950408889634f;  // scale * log2(e)
        int h = t >> 6, c = t & 63;
        float s = 0.f;
        #pragma unroll 8
        for (int m = 0; m < 64; ++m) s = fmaf(ash[h][m], W2[m * 64 + c], s);
        atil[h][c] = s * SC;
    }
    __syncthreads();

    // ---- per-lane constants (SiLU's 0.5 folded into W1/b1) ----
    const int j0 = lane, j1 = lane + 32;
    const float ka0 = 0.5f * W1[2 * j0], kb0 = 0.5f * W1[2 * j0 + 1], kc0 = 0.5f * b1[j0];
    const float ka1 = 0.5f * W1[2 * j1], kb1 = 0.5f * W1[2 * j1 + 1], kc1 = 0.5f * b1[j1];
    float A0[NHEADS], A1[NHEADS];
    #pragma unroll
    for (int h = 0; h < NHEADS; ++h) { A0[h] = atil[h][j0]; A1[h] = atil[h][j1]; }

    // Packed accumulators: (head pair) x (dim j0/j1)
    u64 acc0_01 = 0, acc0_23 = 0, acc1_01 = 0, acc1_23 = 0;
    float zloc = 0.f;   // lane-local sum of this lane's own em values

    const int gwarp  = (blockIdx.x * blockDim.x + t) >> 5;
    const int nwarps = (gridDim.x * blockDim.x) >> 5;
    const int M = N >> 4;                       // 16-pt super-groups
    const int chunk = (M + nwarps - 1) / nwarps;
    const int ms = gwarp * chunk;
    const int me = min(M, ms + chunk);

    const float4* rr4 = (const float4*)rr;
    const float4* ri4 = (const float4*)ri;
    const bool hi16 = (lane & 16) != 0;

    for (int m = ms; m < me; ++m) {
        // ---- all 16 points' loads issue back-to-back (one latency wait) ----
        float4 rA0 = __ldg(rr4 + 4 * m),     rA1 = __ldg(rr4 + 4 * m + 1);
        float4 rB0 = __ldg(rr4 + 4 * m + 2), rB1 = __ldg(rr4 + 4 * m + 3);
        float4 iA0 = __ldg(ri4 + 4 * m),     iA1 = __ldg(ri4 + 4 * m + 1);
        float4 iB0 = __ldg(ri4 + 4 * m + 2), iB1 = __ldg(ri4 + 4 * m + 3);

        // ---- half A: MLP + SiLU ----
        float reA[8] = {rA0.x, rA0.y, rA0.z, rA0.w, rA1.x, rA1.y, rA1.z, rA1.w};
        float imA[8] = {iA0.x, iA0.y, iA0.z, iA0.w, iA1.x, iA1.y, iA1.z, iA1.w};
        float u0A[8], u1A[8];
        #pragma unroll
        for (int pt = 0; pt < 8; ++pt) {
            float h0 = fmaf(ka0, reA[pt], fmaf(kb0, imA[pt], kc0));
            float h1 = fmaf(ka1, reA[pt], fmaf(kb1, imA[pt], kc1));
            u0A[pt] = fmaf(h0, tanh_fast(h0), h0);
            u1A[pt] = fmaf(h1, tanh_fast(h1), h1);
        }
        // ---- half B: MLP + SiLU (independent; fills half-A stall slots) ----
        float reB[8] = {rB0.x, rB0.y, rB0.z, rB0.w, rB1.x, rB1.y, rB1.z, rB1.w};
        float imB[8] = {iB0.x, iB0.y, iB0.z, iB0.w, iB1.x, iB1.y, iB1.z, iB1.w};
        float u0B[8], u1B[8];
        #pragma unroll
        for (int pt = 0; pt < 8; ++pt) {
            float h0 = fmaf(ka0, reB[pt], fmaf(kb0, imB[pt], kc0));
            float h1 = fmaf(ka1, reB[pt], fmaf(kb1, imB[pt], kc1));
            u0B[pt] = fmaf(h0, tanh_fast(h0), h0);
            u1B[pt] = fmaf(h1, tanh_fast(h1), h1);
        }

        // ---- half A: score gen with fused m=16 stage (R7-verified) ----
        float pA[16];
        #pragma unroll
        for (int pt = 0; pt < 4; ++pt) {
            #pragma unroll
            for (int h = 0; h < NHEADS; ++h) {
                float sLo = fmaf(A0[h], u0A[pt],     A1[h] * u1A[pt]);
                float sHi = fmaf(A0[h], u0A[pt + 4], A1[h] * u1A[pt + 4]);
                float keep = hi16 ? sHi : sLo;
                float send = hi16 ? sLo : sHi;
                pA[pt * 4 + h] = keep + __shfl_xor_sync(0xffffffffu, send, 16);
            }
        }
        // ---- half B: score gen with fused m=16 stage ----
        float pB[16];
        #pragma unroll
        for (int pt = 0; pt < 4; ++pt) {
            #pragma unroll
            for (int h = 0; h < NHEADS; ++h) {
                float sLo = fmaf(A0[h], u0B[pt],     A1[h] * u1B[pt]);
                float sHi = fmaf(A0[h], u0B[pt + 4], A1[h] * u1B[pt + 4]);
                float keep = hi16 ? sHi : sLo;
                float send = hi16 ? sLo : sHi;
                pB[pt * 4 + h] = keep + __shfl_xor_sync(0xffffffffu, send, 16);
            }
        }
        // ---- butterflies, stages m=8..1 (two independent chains) ----
        #pragma unroll
        for (int s = 8; s >= 1; s >>= 1) {
            const bool hi = (lane & s) != 0;
            #pragma unroll
            for (int i = 0; i < s; ++i) {
                float keepA = hi ? pA[i + s] : pA[i];
                float sendA = hi ? pA[i] : pA[i + s];
                pA[i] = keepA + __shfl_xor_sync(0xffffffffu, sendA, s);
                float keepB = hi ? pB[i + s] : pB[i];
                float sendB = hi ? pB[i] : pB[i + s];
                pB[i] = keepB + __shfl_xor_sync(0xffffffffu, sendB, s);
            }
        }
        float emA = exp2_fast(pA[0]);   // exp(score(ptA=lane>>2, h=lane&3))
        float emB = exp2_fast(pB[0]);   // exp(score(ptB=lane>>2, h=lane&3))
        zloc += emA + emB;
        // ---- broadcast 64 weights via smem (parity double-buffered) ----
        float* wrow = &wb[wid][m & 1][0];
        wrow[lane] = emA; wrow[lane + 32] = emB;
        __syncwarp();
        const float4* wp = (const float4*)wrow;
        #pragma unroll
        for (int pt = 0; pt < 8; ++pt) {
            float4 w4 = wp[pt];                      // half A weights, pt
            u64 W01 = pack2(w4.x, w4.y), W23 = pack2(w4.z, w4.w);
            u64 D0 = pack2(u0A[pt], u0A[pt]), D1 = pack2(u1A[pt], u1A[pt]);
            acc0_01 = fma2(W01, D0, acc0_01);
            acc0_23 = fma2(W23, D0, acc0_23);
            acc1_01 = fma2(W01, D1, acc1_01);
            acc1_23 = fma2(W23, D1, acc1_23);
        }
        #pragma unroll
        for (int pt = 0; pt < 8; ++pt) {
            float4 w4 = wp[pt + 8];                  // half B weights, pt
            u64 W01 = pack2(w4.x, w4.y), W23 = pack2(w4.z, w4.w);
            u64 D0 = pack2(u0B[pt], u0B[pt]), D1 = pack2(u1B[pt], u1B[pt]);
            acc0_01 = fma2(W01, D0, acc0_01);
            acc0_23 = fma2(W23, D0, acc0_23);
            acc1_01 = fma2(W01, D1, acc1_01);
            acc1_23 = fma2(W23, D1, acc1_23);
        }
    }

    float acc0[NHEADS], acc1[NHEADS];
    unpack2(acc0_01, acc0[0], acc0[1]); unpack2(acc0_23, acc0[2], acc0[3]);
    unpack2(acc1_01, acc1[0], acc1[1]); unpack2(acc1_23, acc1[2], acc1[3]);

    // Tail points (N % 16): warp 0 only, scalar butterfly path.
    float ztl[NHEADS] = {0.f, 0.f, 0.f, 0.f};
    if (gwarp == 0) {
        for (int n = (M << 4); n < N; ++n) {
            float re = rr[n], im = ri[n];
            float h0 = fmaf(ka0, re, fmaf(kb0, im, kc0));
            float h1 = fmaf(ka1, re, fmaf(kb1, im, kc1));
            float v0 = fmaf(h0, tanh_fast(h0), h0);
            float v1 = fmaf(h1, tanh_fast(h1), h1);
            #pragma unroll
            for (int h = 0; h < NHEADS; ++h) {
                float s = fmaf(A0[h], v0, A1[h] * v1);
                #pragma unroll
                for (int mm = 16; mm >= 1; mm >>= 1)
                    s += __shfl_xor_sync(0xffffffffu, s, mm);
                float w = exp2_fast(s);
                ztl[h] += w;
                acc0[h] = fmaf(w, v0, acc0[h]);
                acc1[h] = fmaf(w, v1, acc1[h]);
            }
        }
    }

    // Commit warp partials (lane-distinct addresses; no intra-warp contention)
    #pragma unroll
    for (int h = 0; h < NHEADS; ++h) {
        atomicAdd(&g_S[h][j0], acc0[h]);
        atomicAdd(&g_S[h][j1], acc1[h]);
    }
    // zloc at lane l belongs to head h=l&3; same-h lanes differ in bits {2,3,4}
    float zs = zloc + __shfl_xor_sync(0xffffffffu, zloc, 16);
    zs += __shfl_xor_sync(0xffffffffu, zs, 8);
    zs += __shfl_xor_sync(0xffffffffu, zs, 4);
    if (lane < NHEADS) atomicAdd(&g_z[lane], zs);
    if (gwarp == 0 && lane == 0) {
        #pragma unroll
        for (int h = 0; h < NHEADS; ++h) atomicAdd(&g_z[h], ztl[h]);
    }

    // ---- epilogue: last block computes the output -------------------------
    // RACE FIX: every thread fences its own atomics; the block barrier then
    // guarantees ALL warps of this block have fenced before thread 0 counts
    // the block as done.
    __threadfence();
    __syncthreads();
    if (t == 0) {
        unsigned v = atomicAdd(&g_ctr, 1u);
        isLast = (v == gridDim.x - 1);
        if (isLast) g_ctr = 0;           // all blocks incremented; safe reset
    }
    __syncthreads();
    if (!isLast) return;

    float* hbar = &ash[0][0];            // reuse [4][64]
    float* pooled = qsh;                 // reuse [64]
    if (t < NHEADS) invz[t] = __frcp_rn(__ldcg(&g_z[t]));
    __syncthreads();
    {
        int h = t >> 6, j = t & 63;
        float s = 0.f;
        #pragma unroll 8
        for (int mm = 0; mm < 64; ++mm)
            s = fmaf(W2[j * 64 + mm], __ldcg(&g_S[h][mm]), s);
        hbar[h * 64 + j] = fmaf(s, invz[h], b2[j]);
    }
    __syncthreads();
    // scratch reset for next graph replay (all reads of g_S/g_z done)
    ((float*)g_S)[t] = 0.f;
    if (t < NHEADS) g_z[t] = 0.f;
    if (t < 64) {
        int h = t >> 4;
        float s = ipb[128 + t];          // Wv row (128+t) dot hbar_h + bv
        #pragma unroll 8
        for (int mm = 0; mm < 64; ++mm)
            s = fmaf(ipw[(128 + t) * 64 + mm], hbar[h * 64 + mm], s);
        pooled[t] = s;
    }
    __syncthreads();
    if (t < 64) {
        float s = opb[t];
        #pragma unroll 8
        for (int k = 0; k < 64; ++k) s = fmaf(opw[t * 64 + k], pooled[k], s);
        out[t] = s;
    }
}

// ---------------------------------------------------------------------------
extern "C" void kernel_launch(void* const* d_in, const int* in_sizes, int n_in,
                              void* d_out, int out_size) {
    // Inputs (metadata order): rho_real, rho_imag, l_A, l_B, [Z_A, Z_B,]
    // W1, b1, W2, b2, query, in_proj_w, in_proj_b, out_proj_w, out_proj_b.
    const float* rr    = (const float*)d_in[0];
    const float* ri    = (const float*)d_in[1];
    const float* W1    = (const float*)d_in[n_in - 9];
    const float* b1    = (const float*)d_in[n_in - 8];
    const float* W2    = (const float*)d_in[n_in - 7];
    const float* b2    = (const float*)d_in[n_in - 6];
    const float* query = (const float*)d_in[n_in - 5];
    const float* ipw   = (const float*)d_in[n_in - 4];
    const float* ipb   = (const float*)d_in[n_in - 3];
    const float* opw   = (const float*)d_in[n_in - 2];
    const float* opb   = (const float*)d_in[n_in - 1];
    int N = in_sizes[0];

    main_kernel<<<296, 256>>>(rr, ri, W1, b1, W2, query, ipw, ipb,
                              b2, opw, opb, (float*)d_out, N);
}

// round 13
// speedup vs baseline: 1.1744x; 1.0120x over previous
#include <cuda_runtime.h>

#define NHEADS 4
typedef unsigned long long u64;

// Scratch (allocation-free). Zero at module load; epilogue re-zeroes after
// reading so every graph replay observes zeros (deterministic).
__device__ float g_S[NHEADS][64];          // sum_n w[h,n] * u_n
__device__ float g_z[NHEADS];              // sum_n w[h,n]
__device__ unsigned int g_ctr;             // last-block-done counter

__device__ __forceinline__ float tanh_fast(float x) {
    float y; asm("tanh.approx.f32 %0, %1;" : "=f"(y) : "f"(x)); return y;
}
__device__ __forceinline__ float exp2_fast(float x) {
    float y; asm("ex2.approx.f32 %0, %1;" : "=f"(y) : "f"(x)); return y;
}
// ---- packed f32x2 helpers (accumulation only) ----
__device__ __forceinline__ u64 pack2(float lo, float hi) {
    u64 r; asm("mov.b64 %0, {%1, %2};" : "=l"(r) : "f"(lo), "f"(hi)); return r;
}
__device__ __forceinline__ void unpack2(u64 v, float& lo, float& hi) {
    asm("mov.b64 {%0, %1}, %2;" : "=f"(lo), "=f"(hi) : "l"(v));
}
__device__ __forceinline__ u64 fma2(u64 a, u64 b, u64 c) {
    u64 d; asm("fma.rn.f32x2 %0, %1, %2, %3;" : "=l"(d) : "l"(a), "l"(b), "l"(c)); return d;
}

// ---------------------------------------------------------------------------
// Single fused kernel (R12 structure + instruction diet).
// Main loop: warp cooperates; lane l owns hidden dims j0=l, j1=l+32.
//   16 points/iteration as TWO independent 8-pt halves (A and B) whose shfl
//   chains interleave. Fused m=16 butterfly stage uses INPUT selection
//   (scores are linear in u, so selecting the u inputs == selecting the
//   score; 4 SELs per point-pair instead of 2 per entry). Accumulation
//   reads weights as ulonglong2 (LDS.128 -> f32x2 pairs, zero pack MOVs).
// Epilogue: last finished block computes hbar/pooled/out, re-zeroes scratch.
//   (Race fix retained: all-thread fence + __syncthreads BEFORE counting.)
// ---------------------------------------------------------------------------
__global__ void __launch_bounds__(256, 2)
main_kernel(const float* __restrict__ rr,
            const float* __restrict__ ri,
            const float* __restrict__ W1,
            const float* __restrict__ b1,
            const float* __restrict__ W2,
            const float* __restrict__ query,
            const float* __restrict__ ipw,
            const float* __restrict__ ipb,
            const float* __restrict__ b2,
            const float* __restrict__ opw,
            const float* __restrict__ opb,
            float* __restrict__ out,
            int N) {
    __shared__ float qsh[64];
    __shared__ float ash[NHEADS][64];     // reused as hbar in epilogue
    __shared__ float atil[NHEADS][64];
    __shared__ float wb[8][2][64];        // per-warp parity-buffered weights
    __shared__ float invz[NHEADS];
    __shared__ bool  isLast;

    const int t    = threadIdx.x;
    const int lane = t & 31;
    const int wid  = t >> 5;

    // ---- prologue: q = query @ Wq^T + bq (4 threads per output) ----
    {
        int o = t >> 2, part = t & 3;
        float s = 0.f;
        const float* row = ipw + o * 64 + part * 16;
        const float* qp  = query + part * 16;
        #pragma unroll
        for (int i = 0; i < 16; ++i) s = fmaf(qp[i], row[i], s);
        s += __shfl_xor_sync(0xffffffffu, s, 1);
        s += __shfl_xor_sync(0xffffffffu, s, 2);
        if (part == 0) qsh[o] = s + ipb[o];
    }
    __syncthreads();
    // ---- a_h[c] = sum_d q[16h+d] * Wk[16h+d, c]  (Wk = ipw rows [64,128)) ----
    {
        int h = t >> 6, c = t & 63;
        float a = 0.f;
        #pragma unroll 4
        for (int d = 0; d < 16; ++d)
            a = fmaf(qsh[16 * h + d], ipw[(64 + 16 * h + d) * 64 + c], a);
        ash[h][c] = a;
    }
    __syncthreads();
    // ---- atil_h[c] = (0.25*log2e) * sum_m a_h[m] * W2[m,c] ----
    {
        const float SC = 0.25f * 1.4426950408889634f;  // scale * log2(e)
        int h = t >> 6, c = t & 63;
        float s = 0.f;
        #pragma unroll 8
        for (int m = 0; m < 64; ++m) s = fmaf(ash[h][m], W2[m * 64 + c], s);
        atil[h][c] = s * SC;
    }
    __syncthreads();

    // ---- per-lane constants (SiLU's 0.5 folded into W1/b1) ----
    const int j0 = lane, j1 = lane + 32;
    const float ka0 = 0.5f * W1[2 * j0], kb0 = 0.5f * W1[2 * j0 + 1], kc0 = 0.5f * b1[j0];
    const float ka1 = 0.5f * W1[2 * j1], kb1 = 0.5f * W1[2 * j1 + 1], kc1 = 0.5f * b1[j1];
    float A0[NHEADS], A1[NHEADS];
    #pragma unroll
    for (int h = 0; h < NHEADS; ++h) { A0[h] = atil[h][j0]; A1[h] = atil[h][j1]; }

    // Packed accumulators: (head pair) x (dim j0/j1)
    u64 acc0_01 = 0, acc0_23 = 0, acc1_01 = 0, acc1_23 = 0;
    float zloc = 0.f;   // lane-local sum of this lane's own em values

    const int gwarp  = (blockIdx.x * blockDim.x + t) >> 5;
    const int nwarps = (gridDim.x * blockDim.x) >> 5;
    const int M = N >> 4;                       // 16-pt super-groups
    const int chunk = (M + nwarps - 1) / nwarps;
    const int ms = gwarp * chunk;
    const int me = min(M, ms + chunk);

    const float4* rr4 = (const float4*)rr + 4 * ms;
    const float4* ri4 = (const float4*)ri + 4 * ms;
    const bool hi16 = (lane & 16) != 0;

    for (int m = ms; m < me; ++m, rr4 += 4, ri4 += 4) {
        // ---- all 16 points' loads issue back-to-back (one latency wait) ----
        float4 rA0 = __ldg(rr4),     rA1 = __ldg(rr4 + 1);
        float4 rB0 = __ldg(rr4 + 2), rB1 = __ldg(rr4 + 3);
        float4 iA0 = __ldg(ri4),     iA1 = __ldg(ri4 + 1);
        float4 iB0 = __ldg(ri4 + 2), iB1 = __ldg(ri4 + 3);

        // ---- half A: MLP + SiLU ----
        float reA[8] = {rA0.x, rA0.y, rA0.z, rA0.w, rA1.x, rA1.y, rA1.z, rA1.w};
        float imA[8] = {iA0.x, iA0.y, iA0.z, iA0.w, iA1.x, iA1.y, iA1.z, iA1.w};
        float u0A[8], u1A[8];
        #pragma unroll
        for (int pt = 0; pt < 8; ++pt) {
            float h0 = fmaf(ka0, reA[pt], fmaf(kb0, imA[pt], kc0));
            float h1 = fmaf(ka1, reA[pt], fmaf(kb1, imA[pt], kc1));
            u0A[pt] = fmaf(h0, tanh_fast(h0), h0);
            u1A[pt] = fmaf(h1, tanh_fast(h1), h1);
        }
        // ---- half B: MLP + SiLU (independent; fills half-A stall slots) ----
        float reB[8] = {rB0.x, rB0.y, rB0.z, rB0.w, rB1.x, rB1.y, rB1.z, rB1.w};
        float imB[8] = {iB0.x, iB0.y, iB0.z, iB0.w, iB1.x, iB1.y, iB1.z, iB1.w};
        float u0B[8], u1B[8];
        #pragma unroll
        for (int pt = 0; pt < 8; ++pt) {
            float h0 = fmaf(ka0, reB[pt], fmaf(kb0, imB[pt], kc0));
            float h1 = fmaf(ka1, reB[pt], fmaf(kb1, imB[pt], kc1));
            u0B[pt] = fmaf(h0, tanh_fast(h0), h0);
            u1B[pt] = fmaf(h1, tanh_fast(h1), h1);
        }

        // ---- half A: score gen with fused m=16 stage (INPUT selection:
        //      scores are linear in u, so selecting the u inputs once per
        //      point-pair replaces per-entry output selection) ----
        float pA[16];
        #pragma unroll
        for (int pt = 0; pt < 4; ++pt) {
            float a0 = hi16 ? u0A[pt + 4] : u0A[pt];
            float a1 = hi16 ? u1A[pt + 4] : u1A[pt];
            float b0 = hi16 ? u0A[pt]     : u0A[pt + 4];
            float b1v = hi16 ? u1A[pt]    : u1A[pt + 4];
            #pragma unroll
            for (int h = 0; h < NHEADS; ++h) {
                float k = fmaf(A0[h], a0, A1[h] * a1);     // this lane's half
                float s = fmaf(A0[h], b0, A1[h] * b1v);    // partner's half
                pA[pt * 4 + h] = k + __shfl_xor_sync(0xffffffffu, s, 16);
            }
        }
        // ---- half B: same ----
        float pB[16];
        #pragma unroll
        for (int pt = 0; pt < 4; ++pt) {
            float a0 = hi16 ? u0B[pt + 4] : u0B[pt];
            float a1 = hi16 ? u1B[pt + 4] : u1B[pt];
            float b0 = hi16 ? u0B[pt]     : u0B[pt + 4];
            float b1v = hi16 ? u1B[pt]    : u1B[pt + 4];
            #pragma unroll
            for (int h = 0; h < NHEADS; ++h) {
                float k = fmaf(A0[h], a0, A1[h] * a1);
                float s = fmaf(A0[h], b0, A1[h] * b1v);
                pB[pt * 4 + h] = k + __shfl_xor_sync(0xffffffffu, s, 16);
            }
        }
        // ---- butterflies, stages m=8..1 (two independent chains) ----
        #pragma unroll
        for (int s = 8; s >= 1; s >>= 1) {
            const bool hi = (lane & s) != 0;
            #pragma unroll
            for (int i = 0; i < s; ++i) {
                float keepA = hi ? pA[i + s] : pA[i];
                float sendA = hi ? pA[i] : pA[i + s];
                pA[i] = keepA + __shfl_xor_sync(0xffffffffu, sendA, s);
                float keepB = hi ? pB[i + s] : pB[i];
                float sendB = hi ? pB[i] : pB[i + s];
                pB[i] = keepB + __shfl_xor_sync(0xffffffffu, sendB, s);
            }
        }
        float emA = exp2_fast(pA[0]);   // exp(score(ptA=lane>>2, h=lane&3))
        float emB = exp2_fast(pB[0]);   // exp(score(ptB=lane>>2, h=lane&3))
        zloc += emA + emB;
        // ---- broadcast 64 weights via smem (parity double-buffered) ----
        float* wrow = &wb[wid][m & 1][0];
        wrow[lane] = emA; wrow[lane + 32] = emB;
        __syncwarp();
        // Weights read as ulonglong2: (w0,w1),(w2,w3) arrive as f32x2-ready
        // register pairs straight from LDS.128 -> zero pack MOVs.
        const ulonglong2* wp2 = (const ulonglong2*)wrow;
        #pragma unroll
        for (int pt = 0; pt < 8; ++pt) {
            ulonglong2 W = wp2[pt];                  // half A weights, pt
            u64 D0 = pack2(u0A[pt], u0A[pt]), D1 = pack2(u1A[pt], u1A[pt]);
            acc0_01 = fma2(W.x, D0, acc0_01);
            acc0_23 = fma2(W.y, D0, acc0_23);
            acc1_01 = fma2(W.x, D1, acc1_01);
            acc1_23 = fma2(W.y, D1, acc1_23);
        }
        #pragma unroll
        for (int pt = 0; pt < 8; ++pt) {
            ulonglong2 W = wp2[pt + 8];              // half B weights, pt
            u64 D0 = pack2(u0B[pt], u0B[pt]), D1 = pack2(u1B[pt], u1B[pt]);
            acc0_01 = fma2(W.x, D0, acc0_01);
            acc0_23 = fma2(W.y, D0, acc0_23);
            acc1_01 = fma2(W.x, D1, acc1_01);
            acc1_23 = fma2(W.y, D1, acc1_23);
        }
    }

    float acc0[NHEADS], acc1[NHEADS];
    unpack2(acc0_01, acc0[0], acc0[1]); unpack2(acc0_23, acc0[2], acc0[3]);
    unpack2(acc1_01, acc1[0], acc1[1]); unpack2(acc1_23, acc1[2], acc1[3]);

    // Tail points (N % 16): warp 0 only, scalar butterfly path.
    float ztl[NHEADS] = {0.f, 0.f, 0.f, 0.f};
    if (gwarp == 0) {
        for (int n = (M << 4); n < N; ++n) {
            float re = rr[n], im = ri[n];
            float h0 = fmaf(ka0, re, fmaf(kb0, im, kc0));
            float h1 = fmaf(ka1, re, fmaf(kb1, im, kc1));
            float v0 = fmaf(h0, tanh_fast(h0), h0);
            float v1 = fmaf(h1, tanh_fast(h1), h1);
            #pragma unroll
            for (int h = 0; h < NHEADS; ++h) {
                float s = fmaf(A0[h], v0, A1[h] * v1);
                #pragma unroll
                for (int mm = 16; mm >= 1; mm >>= 1)
                    s += __shfl_xor_sync(0xffffffffu, s, mm);
                float w = exp2_fast(s);
                ztl[h] += w;
                acc0[h] = fmaf(w, v0, acc0[h]);
                acc1[h] = fmaf(w, v1, acc1[h]);
            }
        }
    }

    // Commit warp partials (lane-distinct addresses; no intra-warp contention)
    #pragma unroll
    for (int h = 0; h < NHEADS; ++h) {
        atomicAdd(&g_S[h][j0], acc0[h]);
        atomicAdd(&g_S[h][j1], acc1[h]);
    }
    // zloc at lane l belongs to head h=l&3; same-h lanes differ in bits {2,3,4}
    float zs = zloc + __shfl_xor_sync(0xffffffffu, zloc, 16);
    zs += __shfl_xor_sync(0xffffffffu, zs, 8);
    zs += __shfl_xor_sync(0xffffffffu, zs, 4);
    if (lane < NHEADS) atomicAdd(&g_z[lane], zs);
    if (gwarp == 0 && lane == 0) {
        #pragma unroll
        for (int h = 0; h < NHEADS; ++h) atomicAdd(&g_z[h], ztl[h]);
    }

    // ---- epilogue: last block computes the output -------------------------
    // RACE FIX: every thread fences its own atomics; the block barrier then
    // guarantees ALL warps of this block have fenced before thread 0 counts
    // the block as done.
    __threadfence();
    __syncthreads();
    if (t == 0) {
        unsigned v = atomicAdd(&g_ctr, 1u);
        isLast = (v == gridDim.x - 1);
        if (isLast) g_ctr = 0;           // all blocks incremented; safe reset
    }
    __syncthreads();
    if (!isLast) return;

    float* hbar = &ash[0][0];            // reuse [4][64]
    float* pooled = qsh;                 // reuse [64]
    if (t < NHEADS) invz[t] = __frcp_rn(__ldcg(&g_z[t]));
    __syncthreads();
    {
        int h = t >> 6, j = t & 63;
        float s = 0.f;
        #pragma unroll 8
        for (int mm = 0; mm < 64; ++mm)
            s = fmaf(W2[j * 64 + mm], __ldcg(&g_S[h][mm]), s);
        hbar[h * 64 + j] = fmaf(s, invz[h], b2[j]);
    }
    __syncthreads();
    // scratch reset for next graph replay (all reads of g_S/g_z done)
    ((float*)g_S)[t] = 0.f;
    if (t < NHEADS) g_z[t] = 0.f;
    if (t < 64) {
        int h = t >> 4;
        float s = ipb[128 + t];          // Wv row (128+t) dot hbar_h + bv
        #pragma unroll 8
        for (int mm = 0; mm < 64; ++mm)
            s = fmaf(ipw[(128 + t) * 64 + mm], hbar[h * 64 + mm], s);
        pooled[t] = s;
    }
    __syncthreads();
    if (t < 64) {
        float s = opb[t];
        #pragma unroll 8
        for (int k = 0; k < 64; ++k) s = fmaf(opw[t * 64 + k], pooled[k], s);
        out[t] = s;
    }
}

// ---------------------------------------------------------------------------
extern "C" void kernel_launch(void* const* d_in, const int* in_sizes, int n_in,
                              void* d_out, int out_size) {
    // Inputs (metadata order): rho_real, rho_imag, l_A, l_B, [Z_A, Z_B,]
    // W1, b1, W2, b2, query, in_proj_w, in_proj_b, out_proj_w, out_proj_b.
    const float* rr    = (const float*)d_in[0];
    const float* ri    = (const float*)d_in[1];
    const float* W1    = (const float*)d_in[n_in - 9];
    const float* b1    = (const float*)d_in[n_in - 8];
    const float* W2    = (const float*)d_in[n_in - 7];
    const float* b2    = (const float*)d_in[n_in - 6];
    const float* query = (const float*)d_in[n_in - 5];
    const float* ipw   = (const float*)d_in[n_in - 4];
    const float* ipb   = (const float*)d_in[n_in - 3];
    const float* opw   = (const float*)d_in[n_in - 2];
    const float* opb   = (const float*)d_in[n_in - 1];
    int N = in_sizes[0];

    main_kernel<<<296, 256>>>(rr, ri, W1, b1, W2, query, ipw, ipb,
                              b2, opw, opb, (float*)d_out, N);
}

// round 14
// speedup vs baseline: 1.2043x; 1.0255x over previous
#include <cuda_runtime.h>

#define NHEADS 4
typedef unsigned long long u64;

// Scratch (allocation-free). Zero at module load; epilogue re-zeroes after
// reading so every graph replay observes zeros (deterministic).
__device__ float g_S[NHEADS][64];          // sum_n w[h,n] * u_n
__device__ float g_z[NHEADS];              // sum_n w[h,n]
__device__ unsigned int g_ctr;             // last-block-done counter

__device__ __forceinline__ float tanh_fast(float x) {
    float y; asm("tanh.approx.f32 %0, %1;" : "=f"(y) : "f"(x)); return y;
}
__device__ __forceinline__ float exp2_fast(float x) {
    float y; asm("ex2.approx.f32 %0, %1;" : "=f"(y) : "f"(x)); return y;
}
// ---- packed f32x2 helpers ----
__device__ __forceinline__ u64 pack2(float lo, float hi) {
    u64 r; asm("mov.b64 %0, {%1, %2};" : "=l"(r) : "f"(lo), "f"(hi)); return r;
}
__device__ __forceinline__ void unpack2(u64 v, float& lo, float& hi) {
    asm("mov.b64 {%0, %1}, %2;" : "=f"(lo), "=f"(hi) : "l"(v));
}
__device__ __forceinline__ u64 fma2(u64 a, u64 b, u64 c) {
    u64 d; asm("fma.rn.f32x2 %0, %1, %2, %3;" : "=l"(d) : "l"(a), "l"(b), "l"(c)); return d;
}
__device__ __forceinline__ u64 mul2(u64 a, u64 b) {
    u64 d; asm("mul.rn.f32x2 %0, %1, %2;" : "=l"(d) : "l"(a), "l"(b)); return d;
}
__device__ __forceinline__ u64 add2(u64 a, u64 b) {
    u64 d; asm("add.rn.f32x2 %0, %1, %2;" : "=l"(d) : "l"(a), "l"(b)); return d;
}

// ---------------------------------------------------------------------------
// Single fused kernel (R13 + packed dual-chain butterfly).
// Main loop: warp cooperates; lane l owns hidden dims j0=l, j1=l+32.
//   16 points/iteration as two independent 8-pt halves (A, B). The two
//   score butterflies are PACKED into one f32x2 chain: pAB[i] carries
//   (chainA value i, chainB value i); lane-bit SEL / shfl_xor / add act
//   componentwise, so one packed butterfly == both scalar ones exactly.
//   Fused m=16 stage by input selection (scores linear in u). Weights
//   broadcast via smem LDS.128 (parity buffered); accumulation f32x2.
// Epilogue: last finished block computes hbar/pooled/out, re-zeroes scratch.
//   (Race fix retained: all-thread fence + __syncthreads BEFORE counting.)
// ---------------------------------------------------------------------------
__global__ void __launch_bounds__(256, 2)
main_kernel(const float* __restrict__ rr,
            const float* __restrict__ ri,
            const float* __restrict__ W1,
            const float* __restrict__ b1,
            const float* __restrict__ W2,
            const float* __restrict__ query,
            const float* __restrict__ ipw,
            const float* __restrict__ ipb,
            const float* __restrict__ b2,
            const float* __restrict__ opw,
            const float* __restrict__ opb,
            float* __restrict__ out,
            int N) {
    __shared__ float qsh[64];
    __shared__ float ash[NHEADS][64];     // reused as hbar in epilogue
    __shared__ float atil[NHEADS][64];
    __shared__ float wb[8][2][64];        // per-warp parity-buffered weights
    __shared__ float invz[NHEADS];
    __shared__ bool  isLast;

    const int t    = threadIdx.x;
    const int lane = t & 31;
    const int wid  = t >> 5;

    // ---- prologue: q = query @ Wq^T + bq (4 threads per output) ----
    {
        int o = t >> 2, part = t & 3;
        float s = 0.f;
        const float* row = ipw + o * 64 + part * 16;
        const float* qp  = query + part * 16;
        #pragma unroll
        for (int i = 0; i < 16; ++i) s = fmaf(qp[i], row[i], s);
        s += __shfl_xor_sync(0xffffffffu, s, 1);
        s += __shfl_xor_sync(0xffffffffu, s, 2);
        if (part == 0) qsh[o] = s + ipb[o];
    }
    __syncthreads();
    // ---- a_h[c] = sum_d q[16h+d] * Wk[16h+d, c]  (Wk = ipw rows [64,128)) ----
    {
        int h = t >> 6, c = t & 63;
        float a = 0.f;
        #pragma unroll 4
        for (int d = 0; d < 16; ++d)
            a = fmaf(qsh[16 * h + d], ipw[(64 + 16 * h + d) * 64 + c], a);
        ash[h][c] = a;
    }
    __syncthreads();
    // ---- atil_h[c] = (0.25*log2e) * sum_m a_h[m] * W2[m,c] ----
    {
        const float SC = 0.25f * 1.4426950408889634f;  // scale * log2(e)
        int h = t >> 6, c = t & 63;
        float s = 0.f;
        #pragma unroll 8
        for (int m = 0; m < 64; ++m) s = fmaf(ash[h][m], W2[m * 64 + c], s);
        atil[h][c] = s * SC;
    }
    __syncthreads();

    // ---- per-lane constants (SiLU's 0.5 folded into W1/b1) ----
    const int j0 = lane, j1 = lane + 32;
    const float ka0 = 0.5f * W1[2 * j0], kb0 = 0.5f * W1[2 * j0 + 1], kc0 = 0.5f * b1[j0];
    const float ka1 = 0.5f * W1[2 * j1], kb1 = 0.5f * W1[2 * j1 + 1], kc1 = 0.5f * b1[j1];
    // Dup-packed score vectors (for the packed dual-chain score-gen).
    u64 P_A0[NHEADS], P_A1[NHEADS];
    #pragma unroll
    for (int h = 0; h < NHEADS; ++h) {
        P_A0[h] = pack2(atil[h][j0], atil[h][j0]);
        P_A1[h] = pack2(atil[h][j1], atil[h][j1]);
    }

    // Packed accumulators: (head pair) x (dim j0/j1)
    u64 acc0_01 = 0, acc0_23 = 0, acc1_01 = 0, acc1_23 = 0;
    float zloc = 0.f;   // lane-local sum of this lane's own em values

    const int gwarp  = (blockIdx.x * blockDim.x + t) >> 5;
    const int nwarps = (gridDim.x * blockDim.x) >> 5;
    const int M = N >> 4;                       // 16-pt super-groups
    const int chunk = (M + nwarps - 1) / nwarps;
    const int ms = gwarp * chunk;
    const int me = min(M, ms + chunk);

    const float4* rr4 = (const float4*)rr + 4 * ms;
    const float4* ri4 = (const float4*)ri + 4 * ms;
    const bool hi16 = (lane & 16) != 0;

    for (int m = ms; m < me; ++m, rr4 += 4, ri4 += 4) {
        // ---- all 16 points' loads issue back-to-back (one latency wait) ----
        float4 rA0 = __ldg(rr4),     rA1 = __ldg(rr4 + 1);
        float4 rB0 = __ldg(rr4 + 2), rB1 = __ldg(rr4 + 3);
        float4 iA0 = __ldg(ri4),     iA1 = __ldg(ri4 + 1);
        float4 iB0 = __ldg(ri4 + 2), iB1 = __ldg(ri4 + 3);

        // ---- half A: MLP + SiLU ----
        float reA[8] = {rA0.x, rA0.y, rA0.z, rA0.w, rA1.x, rA1.y, rA1.z, rA1.w};
        float imA[8] = {iA0.x, iA0.y, iA0.z, iA0.w, iA1.x, iA1.y, iA1.z, iA1.w};
        float u0A[8], u1A[8];
        #pragma unroll
        for (int pt = 0; pt < 8; ++pt) {
            float h0 = fmaf(ka0, reA[pt], fmaf(kb0, imA[pt], kc0));
            float h1 = fmaf(ka1, reA[pt], fmaf(kb1, imA[pt], kc1));
            u0A[pt] = fmaf(h0, tanh_fast(h0), h0);
            u1A[pt] = fmaf(h1, tanh_fast(h1), h1);
        }
        // ---- half B: MLP + SiLU (independent; fills half-A stall slots) ----
        float reB[8] = {rB0.x, rB0.y, rB0.z, rB0.w, rB1.x, rB1.y, rB1.z, rB1.w};
        float imB[8] = {iB0.x, iB0.y, iB0.z, iB0.w, iB1.x, iB1.y, iB1.z, iB1.w};
        float u0B[8], u1B[8];
        #pragma unroll
        for (int pt = 0; pt < 8; ++pt) {
            float h0 = fmaf(ka0, reB[pt], fmaf(kb0, imB[pt], kc0));
            float h1 = fmaf(ka1, reB[pt], fmaf(kb1, imB[pt], kc1));
            u0B[pt] = fmaf(h0, tanh_fast(h0), h0);
            u1B[pt] = fmaf(h1, tanh_fast(h1), h1);
        }

        // ---- packed score gen with fused m=16 stage ----
        // Input selection per half (scores are linear in u), then pack the
        // selected scalars so each u64 carries (chainA, chainB). pAB[i]
        // holds value index i for BOTH chains.
        u64 pAB[16];
        #pragma unroll
        for (int pt = 0; pt < 4; ++pt) {
            float a0A = hi16 ? u0A[pt + 4] : u0A[pt];
            float a1A = hi16 ? u1A[pt + 4] : u1A[pt];
            float b0A = hi16 ? u0A[pt]     : u0A[pt + 4];
            float b1A = hi16 ? u1A[pt]     : u1A[pt + 4];
            float a0B = hi16 ? u0B[pt + 4] : u0B[pt];
            float a1B = hi16 ? u1B[pt + 4] : u1B[pt];
            float b0B = hi16 ? u0B[pt]     : u0B[pt + 4];
            float b1B = hi16 ? u1B[pt]     : u1B[pt + 4];
            u64 aw0 = pack2(a0A, a0B), aw1 = pack2(a1A, a1B);
            u64 bw0 = pack2(b0A, b0B), bw1 = pack2(b1A, b1B);
            #pragma unroll
            for (int h = 0; h < NHEADS; ++h) {
                u64 kp = fma2(P_A0[h], aw0, mul2(P_A1[h], aw1));  // own half
                u64 sp = fma2(P_A0[h], bw0, mul2(P_A1[h], bw1));  // partner's
                pAB[pt * 4 + h] = add2(kp, __shfl_xor_sync(0xffffffffu, sp, 16));
            }
        }
        // ---- packed butterfly, stages m=8..1 (both chains at once) ----
        #pragma unroll
        for (int s = 8; s >= 1; s >>= 1) {
            const bool hi = (lane & s) != 0;
            #pragma unroll
            for (int i = 0; i < s; ++i) {
                u64 keep = hi ? pAB[i + s] : pAB[i];
                u64 send = hi ? pAB[i] : pAB[i + s];
                pAB[i] = add2(keep, __shfl_xor_sync(0xffffffffu, send, s));
            }
        }
        float sA, sB; unpack2(pAB[0], sA, sB);
        float emA = exp2_fast(sA);      // exp(score(ptA=lane>>2, h=lane&3))
        float emB = exp2_fast(sB);      // exp(score(ptB=lane>>2, h=lane&3))
        zloc += emA + emB;
        // ---- broadcast 64 weights via smem (parity double-buffered) ----
        float* wrow = &wb[wid][m & 1][0];
        wrow[lane] = emA; wrow[lane + 32] = emB;
        __syncwarp();
        // Weights read as ulonglong2: (w0,w1),(w2,w3) arrive as f32x2-ready
        // register pairs straight from LDS.128 -> zero pack MOVs.
        const ulonglong2* wp2 = (const ulonglong2*)wrow;
        #pragma unroll
        for (int pt = 0; pt < 8; ++pt) {
            ulonglong2 W = wp2[pt];                  // half A weights, pt
            u64 D0 = pack2(u0A[pt], u0A[pt]), D1 = pack2(u1A[pt], u1A[pt]);
            acc0_01 = fma2(W.x, D0, acc0_01);
            acc0_23 = fma2(W.y, D0, acc0_23);
            acc1_01 = fma2(W.x, D1, acc1_01);
            acc1_23 = fma2(W.y, D1, acc1_23);
        }
        #pragma unroll
        for (int pt = 0; pt < 8; ++pt) {
            ulonglong2 W = wp2[pt + 8];              // half B weights, pt
            u64 D0 = pack2(u0B[pt], u0B[pt]), D1 = pack2(u1B[pt], u1B[pt]);
            acc0_01 = fma2(W.x, D0, acc0_01);
            acc0_23 = fma2(W.y, D0, acc0_23);
            acc1_01 = fma2(W.x, D1, acc1_01);
            acc1_23 = fma2(W.y, D1, acc1_23);
        }
    }

    float acc0[NHEADS], acc1[NHEADS];
    unpack2(acc0_01, acc0[0], acc0[1]); unpack2(acc0_23, acc0[2], acc0[3]);
    unpack2(acc1_01, acc1[0], acc1[1]); unpack2(acc1_23, acc1[2], acc1[3]);

    // Tail points (N % 16): warp 0 only, scalar butterfly path (atil via smem).
    float ztl[NHEADS] = {0.f, 0.f, 0.f, 0.f};
    if (gwarp == 0) {
        for (int n = (M << 4); n < N; ++n) {
            float re = rr[n], im = ri[n];
            float h0 = fmaf(ka0, re, fmaf(kb0, im, kc0));
            float h1 = fmaf(ka1, re, fmaf(kb1, im, kc1));
            float v0 = fmaf(h0, tanh_fast(h0), h0);
            float v1 = fmaf(h1, tanh_fast(h1), h1);
            #pragma unroll
            for (int h = 0; h < NHEADS; ++h) {
                float s = fmaf(atil[h][j0], v0, atil[h][j1] * v1);
                #pragma unroll
                for (int mm = 16; mm >= 1; mm >>= 1)
                    s += __shfl_xor_sync(0xffffffffu, s, mm);
                float w = exp2_fast(s);
                ztl[h] += w;
                acc0[h] = fmaf(w, v0, acc0[h]);
                acc1[h] = fmaf(w, v1, acc1[h]);
            }
        }
    }

    // Commit warp partials (lane-distinct addresses; no intra-warp contention)
    #pragma unroll
    for (int h = 0; h < NHEADS; ++h) {
        atomicAdd(&g_S[h][j0], acc0[h]);
        atomicAdd(&g_S[h][j1], acc1[h]);
    }
    // zloc at lane l belongs to head h=l&3; same-h lanes differ in bits {2,3,4}
    float zs = zloc + __shfl_xor_sync(0xffffffffu, zloc, 16);
    zs += __shfl_xor_sync(0xffffffffu, zs, 8);
    zs += __shfl_xor_sync(0xffffffffu, zs, 4);
    if (lane < NHEADS) atomicAdd(&g_z[lane], zs);
    if (gwarp == 0 && lane == 0) {
        #pragma unroll
        for (int h = 0; h < NHEADS; ++h) atomicAdd(&g_z[h], ztl[h]);
    }

    // ---- epilogue: last block computes the output -------------------------
    // RACE FIX: every thread fences its own atomics; the block barrier then
    // guarantees ALL warps of this block have fenced before thread 0 counts
    // the block as done.
    __threadfence();
    __syncthreads();
    if (t == 0) {
        unsigned v = atomicAdd(&g_ctr, 1u);
        isLast = (v == gridDim.x - 1);
        if (isLast) g_ctr = 0;           // all blocks incremented; safe reset
    }
    __syncthreads();
    if (!isLast) return;

    float* hbar = &ash[0][0];            // reuse [4][64]
    float* pooled = qsh;                 // reuse [64]
    if (t < NHEADS) invz[t] = __frcp_rn(__ldcg(&g_z[t]));
    __syncthreads();
    {
        int h = t >> 6, j = t & 63;
        float s = 0.f;
        #pragma unroll 8
        for (int mm = 0; mm < 64; ++mm)
            s = fmaf(W2[j * 64 + mm], __ldcg(&g_S[h][mm]), s);
        hbar[h * 64 + j] = fmaf(s, invz[h], b2[j]);
    }
    __syncthreads();
    // scratch reset for next graph replay (all reads of g_S/g_z done)
    ((float*)g_S)[t] = 0.f;
    if (t < NHEADS) g_z[t] = 0.f;
    if (t < 64) {
        int h = t >> 4;
        float s = ipb[128 + t];          // Wv row (128+t) dot hbar_h + bv
        #pragma unroll 8
        for (int mm = 0; mm < 64; ++mm)
            s = fmaf(ipw[(128 + t) * 64 + mm], hbar[h * 64 + mm], s);
        pooled[t] = s;
    }
    __syncthreads();
    if (t < 64) {
        float s = opb[t];
        #pragma unroll 8
        for (int k = 0; k < 64; ++k) s = fmaf(opw[t * 64 + k], pooled[k], s);
        out[t] = s;
    }
}

// ---------------------------------------------------------------------------
extern "C" void kernel_launch(void* const* d_in, const int* in_sizes, int n_in,
                              void* d_out, int out_size) {
    // Inputs (metadata order): rho_real, rho_imag, l_A, l_B, [Z_A, Z_B,]
    // W1, b1, W2, b2, query, in_proj_w, in_proj_b, out_proj_w, out_proj_b.
    const float* rr    = (const float*)d_in[0];
    const float* ri    = (const float*)d_in[1];
    const float* W1    = (const float*)d_in[n_in - 9];
    const float* b1    = (const float*)d_in[n_in - 8];
    const float* W2    = (const float*)d_in[n_in - 7];
    const float* b2    = (const float*)d_in[n_in - 6];
    const float* query = (const float*)d_in[n_in - 5];
    const float* ipw   = (const float*)d_in[n_in - 4];
    const float* ipb   = (const float*)d_in[n_in - 3];
    const float* opw   = (const float*)d_in[n_in - 2];
    const float* opb   = (const float*)d_in[n_in - 1];
    int N = in_sizes[0];

    main_kernel<<<296, 256>>>(rr, ri, W1, b1, W2, query, ipw, ipb,
                              b2, opw, opb, (float*)d_out, N);
}